// round 8
// baseline (speedup 1.0000x reference)
#include <cuda_runtime.h>
#include <math.h>
#include <stdint.h>

#define T_TOK 4096
#define H     2048
#define IDIM  1024
#define NE    8
#define NTOT  12
#define CAP   4096
#define SCALE 1.5f

// ---------------- scratch (static device globals; no runtime allocation) ----------------
__device__ int   g_cnt[NE];
__device__ int   g_tok[NE * CAP];
__device__ float g_wt [NE * CAP];
__device__ int   g_dst[NE * CAP];
__device__ float g_zw [T_TOK];
__device__ int   g_mask[T_TOK];
__device__ float g_act [(size_t)NE * CAP * IDIM];     // expert-grouped activations
__device__ float g_pair[(size_t)T_TOK * 2 * H];       // per (token,k) down output

// ---------------- helpers ----------------
__device__ __forceinline__ void cp_async16(void* smem, const void* gmem) {
    uint32_t s = (uint32_t)__cvta_generic_to_shared(smem);
    asm volatile("cp.async.cg.shared.global [%0], [%1], 16;" :: "r"(s), "l"(gmem));
}
#define CP_COMMIT() asm volatile("cp.async.commit_group;")
#define CP_WAIT2()  asm volatile("cp.async.wait_group 2;")

__device__ __forceinline__ uint32_t f2tf32(float f) {
    uint32_t r;
    asm("cvt.rna.tf32.f32 %0, %1;" : "=r"(r) : "f"(f));
    return r;
}

__device__ __forceinline__ void mma_tf32(float c[4],
                                         uint32_t a0, uint32_t a1, uint32_t a2, uint32_t a3,
                                         uint32_t b0, uint32_t b1) {
    asm volatile(
        "mma.sync.aligned.m16n8k8.row.col.f32.tf32.tf32.f32 "
        "{%0,%1,%2,%3}, {%4,%5,%6,%7}, {%8,%9}, {%0,%1,%2,%3};\n"
        : "+f"(c[0]), "+f"(c[1]), "+f"(c[2]), "+f"(c[3])
        : "r"(a0), "r"(a1), "r"(a2), "r"(a3), "r"(b0), "r"(b1));
}

// ---------------- router: one warp per token ----------------
__global__ void router_kernel(const float* __restrict__ x,
                              const float* __restrict__ cw,
                              const float* __restrict__ bias) {
    int warp = threadIdx.x >> 5;
    int lane = threadIdx.x & 31;
    int t = blockIdx.x * 4 + warp;
    if (t >= T_TOK) return;
    const float* xr = x + (size_t)t * H;

    float acc[NTOT];
#pragma unroll
    for (int e = 0; e < NTOT; e++) acc[e] = 0.f;
    for (int h = lane; h < H; h += 32) {
        float xv = xr[h];
#pragma unroll
        for (int e = 0; e < NTOT; e++) acc[e] += xv * __ldg(&cw[e * H + h]);
    }
#pragma unroll
    for (int e = 0; e < NTOT; e++) {
#pragma unroll
        for (int off = 16; off; off >>= 1)
            acc[e] += __shfl_xor_sync(0xffffffffu, acc[e], off);
    }
    if (lane == 0) {
        float m = acc[0];
#pragma unroll
        for (int e = 1; e < NTOT; e++) m = fmaxf(m, acc[e]);
        float p[NTOT];
        float s = 0.f;
#pragma unroll
        for (int e = 0; e < NTOT; e++) { p[e] = expf(acc[e] - m); s += p[e]; }
        float inv = 1.f / s;
        float biased[NTOT];
#pragma unroll
        for (int e = 0; e < NTOT; e++) { p[e] *= inv; biased[e] = p[e] + bias[e]; }

        // top-2 of biased scores (lowest index wins ties, matching jax.lax.top_k)
        int i0 = 0;
#pragma unroll
        for (int e = 1; e < NTOT; e++) if (biased[e] > biased[i0]) i0 = e;
        int i1 = (i0 == 0) ? 1 : 0;
#pragma unroll
        for (int e = 0; e < NTOT; e++)
            if (e != i0 && biased[e] > biased[i1]) i1 = e;

        int sel[2] = { i0, i1 };
        float zw = 0.f;
        int mask = 0;
#pragma unroll
        for (int k = 0; k < 2; k++) {
            int e = sel[k];
            float w = p[e] * SCALE;       // weight uses UNBIASED prob
            if (e < NE) {
                int slot = atomicAdd(&g_cnt[e], 1);
                g_tok[e * CAP + slot] = t;
                g_wt [e * CAP + slot] = w;
                g_dst[e * CAP + slot] = t * 2 + k;
                mask |= (1 << k);
            } else {
                zw += w;
            }
        }
        g_zw[t]  = zw;
        g_mask[t] = mask;
    }
}

// ---------------- grouped gate+up tf32 GEMM, 4-stage cp.async pipeline ----------------
// Block tile: 128 slots x 64 inter, BK=16. 8 warps (4x2). Warp tile 32x32 for
// BOTH gate and up (shared A fragments). Dynamic smem, wait_group 2.
#define GU_BM 128
#define GU_BN 64
#define GU_BK 16
#define GU_IT (H / GU_BK)
#define SMS 20          // k-stride (16 + 4 pad) -> conflict-free fragment LDS
#define NSTG 4

// dynamic smem layout sizes (floats)
#define GU_SA_ST (GU_BM * SMS)               // 2560
#define GU_SG_ST (GU_BN * SMS)               // 1280
#define GU_SMEM_BYTES ((NSTG * (GU_SA_ST + 2 * GU_SG_ST)) * 4 + GU_BM * 4)

__global__ __launch_bounds__(256, 2) void gateup_kernel(const float* __restrict__ x,
                                                        const float* __restrict__ gw,
                                                        const float* __restrict__ uw) {
    int e = blockIdx.z;
    int cnt = g_cnt[e];
    int t0 = blockIdx.y * GU_BM;
    if (t0 >= cnt) return;
    int i0 = blockIdx.x * GU_BN;

    extern __shared__ float dsm[];
    float* SA = dsm;                               // [NSTG][GU_BM][SMS]
    float* SG = SA + NSTG * GU_SA_ST;              // [NSTG][GU_BN][SMS]
    float* SU = SG + NSTG * GU_SG_ST;              // [NSTG][GU_BN][SMS]
    int*   toks = (int*)(SU + NSTG * GU_SG_ST);    // [GU_BM]

    int tid  = threadIdx.x;
    int lane = tid & 31;
    int warp = tid >> 5;
    int wm = warp >> 1;       // 0..3
    int wn = warp & 1;        // 0..1
    int g = lane >> 2;        // 0..7
    int tg = lane & 3;        // 0..3

    if (tid < GU_BM) {
        int s = t0 + tid;
        toks[tid] = g_tok[e * CAP + ((s < cnt) ? s : 0)];
    }
    __syncthreads();

    int r0 = tid >> 2;        // 0..63
    int ch = (tid & 3) * 4;   // 0,4,8,12

    const float* a0 = x + (size_t)toks[r0] * H + ch;
    const float* a1 = x + (size_t)toks[r0 + 64] * H + ch;
    const float* gp = gw + (size_t)e * IDIM * H + (size_t)(i0 + r0) * H + ch;
    const float* up = uw + (size_t)e * IDIM * H + (size_t)(i0 + r0) * H + ch;

    float cg[2][4][4] = {};
    float cu[2][4][4] = {};

    // prologue: chunks 0..2 -> stages 0..2 (3 groups in flight)
#pragma unroll
    for (int s = 0; s < NSTG - 1; s++) {
        int ko = s * GU_BK;
        cp_async16(&SA[s * GU_SA_ST + r0 * SMS + ch], a0 + ko);
        cp_async16(&SA[s * GU_SA_ST + (r0 + 64) * SMS + ch], a1 + ko);
        cp_async16(&SG[s * GU_SG_ST + r0 * SMS + ch], gp + ko);
        cp_async16(&SU[s * GU_SG_ST + r0 * SMS + ch], up + ko);
        CP_COMMIT();
    }

    for (int k = 0; k < GU_IT; k++) {
        CP_WAIT2();            // chunk k complete (<=2 groups outstanding)
        __syncthreads();

        int kn = k + NSTG - 1;
        if (kn < GU_IT) {
            int st = kn & (NSTG - 1);
            int ko = kn * GU_BK;
            cp_async16(&SA[st * GU_SA_ST + r0 * SMS + ch], a0 + ko);
            cp_async16(&SA[st * GU_SA_ST + (r0 + 64) * SMS + ch], a1 + ko);
            cp_async16(&SG[st * GU_SG_ST + r0 * SMS + ch], gp + ko);
            cp_async16(&SU[st * GU_SG_ST + r0 * SMS + ch], up + ko);
        }
        CP_COMMIT();           // one group per iter keeps accounting uniform

        int st = k & (NSTG - 1);
        const float* sa = SA + st * GU_SA_ST;
        const float* sg = SG + st * GU_SG_ST;
        const float* su = SU + st * GU_SG_ST;
#pragma unroll
        for (int ks = 0; ks < GU_BK / 8; ks++) {
            int kb = ks * 8;
            uint32_t a[2][4];
#pragma unroll
            for (int mi = 0; mi < 2; mi++) {
                int rb = wm * 32 + mi * 16;
                a[mi][0] = f2tf32(sa[(rb + g    ) * SMS + kb + tg]);
                a[mi][1] = f2tf32(sa[(rb + g + 8) * SMS + kb + tg]);
                a[mi][2] = f2tf32(sa[(rb + g    ) * SMS + kb + tg + 4]);
                a[mi][3] = f2tf32(sa[(rb + g + 8) * SMS + kb + tg + 4]);
            }
#pragma unroll
            for (int ni = 0; ni < 4; ni++) {
                int nb = wn * 32 + ni * 8 + g;
                uint32_t bg0 = f2tf32(sg[nb * SMS + kb + tg]);
                uint32_t bg1 = f2tf32(sg[nb * SMS + kb + tg + 4]);
                uint32_t bu0 = f2tf32(su[nb * SMS + kb + tg]);
                uint32_t bu1 = f2tf32(su[nb * SMS + kb + tg + 4]);
#pragma unroll
                for (int mi = 0; mi < 2; mi++) {
                    mma_tf32(cg[mi][ni], a[mi][0], a[mi][1], a[mi][2], a[mi][3], bg0, bg1);
                    mma_tf32(cu[mi][ni], a[mi][0], a[mi][1], a[mi][2], a[mi][3], bu0, bu1);
                }
            }
        }
    }

    // epilogue: act = silu(gate) * up
#pragma unroll
    for (int mi = 0; mi < 2; mi++) {
        int rr = wm * 32 + mi * 16 + g;
        int srow0 = t0 + rr;
        int srow1 = srow0 + 8;
        float* row0 = g_act + ((size_t)e * CAP + srow0) * IDIM;
        float* row1 = g_act + ((size_t)e * CAP + srow1) * IDIM;
#pragma unroll
        for (int ni = 0; ni < 4; ni++) {
            int col = i0 + wn * 32 + ni * 8 + tg * 2;
            if (srow0 < cnt) {
                float g0 = cg[mi][ni][0], g1 = cg[mi][ni][1];
                float2 v;
                v.x = (g0 / (1.f + expf(-g0))) * cu[mi][ni][0];
                v.y = (g1 / (1.f + expf(-g1))) * cu[mi][ni][1];
                *(float2*)(row0 + col) = v;
            }
            if (srow1 < cnt) {
                float g2 = cg[mi][ni][2], g3 = cg[mi][ni][3];
                float2 v;
                v.x = (g2 / (1.f + expf(-g2))) * cu[mi][ni][2];
                v.y = (g3 / (1.f + expf(-g3))) * cu[mi][ni][3];
                *(float2*)(row1 + col) = v;
            }
        }
    }
}

// ---------------- grouped down tf32 GEMM, 4-stage cp.async pipeline ----------------
// Block tile: 128 slots x 128 H, BK=16. 8 warps (4x2). Warp tile 32x64.
#define DN_BM 128
#define DN_BN 128
#define DN_BK 16
#define DN_IT (IDIM / DN_BK)
#define DN_SA_ST (DN_BM * SMS)               // 2560
#define DN_SMEM_BYTES ((NSTG * 2 * DN_SA_ST) * 4 + DN_BM * 8)

__global__ __launch_bounds__(256, 2) void down_kernel(const float* __restrict__ dw) {
    int e = blockIdx.z;
    int cnt = g_cnt[e];
    int s0 = blockIdx.y * DN_BM;
    if (s0 >= cnt) return;
    int h0 = blockIdx.x * DN_BN;

    extern __shared__ float dsm[];
    float* SA = dsm;                             // [NSTG][DN_BM][SMS]
    float* SB = SA + NSTG * DN_SA_ST;            // [NSTG][DN_BN][SMS]
    float* wts = SB + NSTG * DN_SA_ST;           // [DN_BM]
    int*   dsts = (int*)(wts + DN_BM);           // [DN_BM]

    int tid  = threadIdx.x;
    int lane = tid & 31;
    int warp = tid >> 5;
    int wm = warp >> 1;      // 0..3
    int wn = warp & 1;       // 0..1
    int g = lane >> 2;
    int tg = lane & 3;

    if (tid < DN_BM) {
        int s = s0 + tid;
        int cs = (s < cnt) ? s : 0;
        wts[tid]  = g_wt [e * CAP + cs];
        dsts[tid] = g_dst[e * CAP + cs];
    }
    __syncthreads();

    int r0 = tid >> 2;       // 0..63
    int ch = (tid & 3) * 4;

    const float* a0 = g_act + ((size_t)e * CAP + s0 + r0) * IDIM + ch;
    const float* a1 = a0 + (size_t)64 * IDIM;
    const float* b0p = dw + (size_t)e * H * IDIM + (size_t)(h0 + r0) * IDIM + ch;
    const float* b1p = b0p + (size_t)64 * IDIM;

    float acc[2][8][4] = {};

#pragma unroll
    for (int s = 0; s < NSTG - 1; s++) {
        int ko = s * DN_BK;
        cp_async16(&SA[s * DN_SA_ST + r0 * SMS + ch], a0 + ko);
        cp_async16(&SA[s * DN_SA_ST + (r0 + 64) * SMS + ch], a1 + ko);
        cp_async16(&SB[s * DN_SA_ST + r0 * SMS + ch], b0p + ko);
        cp_async16(&SB[s * DN_SA_ST + (r0 + 64) * SMS + ch], b1p + ko);
        CP_COMMIT();
    }

    for (int k = 0; k < DN_IT; k++) {
        CP_WAIT2();
        __syncthreads();

        int kn = k + NSTG - 1;
        if (kn < DN_IT) {
            int st = kn & (NSTG - 1);
            int ko = kn * DN_BK;
            cp_async16(&SA[st * DN_SA_ST + r0 * SMS + ch], a0 + ko);
            cp_async16(&SA[st * DN_SA_ST + (r0 + 64) * SMS + ch], a1 + ko);
            cp_async16(&SB[st * DN_SA_ST + r0 * SMS + ch], b0p + ko);
            cp_async16(&SB[st * DN_SA_ST + (r0 + 64) * SMS + ch], b1p + ko);
        }
        CP_COMMIT();

        int st = k & (NSTG - 1);
        const float* sa = SA + st * DN_SA_ST;
        const float* sb = SB + st * DN_SA_ST;
#pragma unroll
        for (int ks = 0; ks < DN_BK / 8; ks++) {
            int kb = ks * 8;
            uint32_t a[2][4];
#pragma unroll
            for (int mi = 0; mi < 2; mi++) {
                int rb = wm * 32 + mi * 16;
                a[mi][0] = f2tf32(sa[(rb + g    ) * SMS + kb + tg]);
                a[mi][1] = f2tf32(sa[(rb + g + 8) * SMS + kb + tg]);
                a[mi][2] = f2tf32(sa[(rb + g    ) * SMS + kb + tg + 4]);
                a[mi][3] = f2tf32(sa[(rb + g + 8) * SMS + kb + tg + 4]);
            }
#pragma unroll
            for (int ni = 0; ni < 8; ni++) {
                int nb = wn * 64 + ni * 8 + g;
                uint32_t b0 = f2tf32(sb[nb * SMS + kb + tg]);
                uint32_t b1 = f2tf32(sb[nb * SMS + kb + tg + 4]);
#pragma unroll
                for (int mi = 0; mi < 2; mi++)
                    mma_tf32(acc[mi][ni], a[mi][0], a[mi][1], a[mi][2], a[mi][3], b0, b1);
            }
        }
    }

#pragma unroll
    for (int mi = 0; mi < 2; mi++) {
        int rr0 = wm * 32 + mi * 16 + g;
        int rr1 = rr0 + 8;
        int srow0 = s0 + rr0;
        int srow1 = s0 + rr1;
        float w0 = wts[rr0], w1 = wts[rr1];
        float* o0 = g_pair + (size_t)dsts[rr0] * H + h0;
        float* o1 = g_pair + (size_t)dsts[rr1] * H + h0;
#pragma unroll
        for (int ni = 0; ni < 8; ni++) {
            int col = wn * 64 + ni * 8 + tg * 2;
            if (srow0 < cnt) {
                float2 v = { acc[mi][ni][0] * w0, acc[mi][ni][1] * w0 };
                *(float2*)(o0 + col) = v;
            }
            if (srow1 < cnt) {
                float2 v = { acc[mi][ni][2] * w1, acc[mi][ni][3] * w1 };
                *(float2*)(o1 + col) = v;
            }
        }
    }
}

// ---------------- combine: out = x*zero_w + valid pair contributions ----------------
__global__ void combine_kernel(const float* __restrict__ x, float* __restrict__ out) {
    int idx = blockIdx.x * blockDim.x + threadIdx.x;
    if (idx >= T_TOK * (H / 4)) return;
    int t  = idx / (H / 4);
    int h4 = idx % (H / 4);
    float4 xv = ((const float4*)x)[idx];
    float zw = g_zw[t];
    int mask = g_mask[t];
    float4 r;
    r.x = xv.x * zw; r.y = xv.y * zw; r.z = xv.z * zw; r.w = xv.w * zw;
    if (mask & 1) {
        float4 p = ((const float4*)(g_pair + (size_t)(t * 2) * H))[h4];
        r.x += p.x; r.y += p.y; r.z += p.z; r.w += p.w;
    }
    if (mask & 2) {
        float4 p = ((const float4*)(g_pair + (size_t)(t * 2 + 1) * H))[h4];
        r.x += p.x; r.y += p.y; r.z += p.z; r.w += p.w;
    }
    ((float4*)out)[idx] = r;
}

// ---------------- launch ----------------
extern "C" void kernel_launch(void* const* d_in, const int* in_sizes, int n_in,
                              void* d_out, int out_size) {
    const float* x    = (const float*)d_in[0];
    const float* cw   = (const float*)d_in[1];
    const float* bias = (const float*)d_in[2];
    const float* gw   = (const float*)d_in[3];
    const float* uw   = (const float*)d_in[4];
    const float* dw   = (const float*)d_in[5];
    float* out = (float*)d_out;

    // Opt-in to >48KB dynamic smem (host attribute set, executes immediately
    // even under graph capture; idempotent).
    cudaFuncSetAttribute(gateup_kernel, cudaFuncAttributeMaxDynamicSharedMemorySize, GU_SMEM_BYTES);
    cudaFuncSetAttribute(down_kernel,   cudaFuncAttributeMaxDynamicSharedMemorySize, DN_SMEM_BYTES);

    void* cntAddr = nullptr;
    cudaGetSymbolAddress(&cntAddr, g_cnt);
    cudaMemsetAsync(cntAddr, 0, NE * sizeof(int));

    router_kernel<<<T_TOK / 4, 128>>>(x, cw, bias);

    dim3 gb(IDIM / GU_BN, T_TOK / GU_BM, NE);
    gateup_kernel<<<gb, 256, GU_SMEM_BYTES>>>(x, gw, uw);

    dim3 gd(H / DN_BN, T_TOK / DN_BM, NE);
    down_kernel<<<gd, 256, DN_SMEM_BYTES>>>(dw);

    int n4 = T_TOK * (H / 4);
    combine_kernel<<<(n4 + 255) / 256, 256>>>(x, out);
}